// round 3
// baseline (speedup 1.0000x reference)
#include <cuda_runtime.h>
#include <cstdint>

#define BB   8
#define LL   2048
#define VV   8192
#define CC   64
#define SS   4              // V-split factor
#define VSUB (VV / SS)      // 2048 verts per CTA
#define TVC  64             // verts per smem chunk
#define NCHK (VSUB / TVC)   // 32 chunks
#define ROWF 132            // scratch row stride (floats)
#define NQ   (BB * LL)      // 16384 output rows

// [SS][B*L][132]: cols 0..63 fL-sum, 64..127 fR-sum, 128 densL, 129 densR
static __device__ float  g_part[SS * NQ * ROWF];
static __device__ float4 g_vn[2 * BB * VV];     // (x,y,z,|v|^2) per (b,side,v)
static __device__ float  g_w1t[132 * 132];      // w1 transposed+padded: w1t[k][j]
static __device__ float  g_b1p[132];
static __device__ float  g_w2p[132];

// ---------- packed f32x2 helpers ----------
__device__ __forceinline__ unsigned long long fma2(unsigned long long a,
                                                   unsigned long long b,
                                                   unsigned long long c) {
    unsigned long long d;
    asm("fma.rn.f32x2 %0, %1, %2, %3;" : "=l"(d) : "l"(a), "l"(b), "l"(c));
    return d;
}
__device__ __forceinline__ unsigned long long pack2(float x, float y) {
    unsigned long long d;
    asm("mov.b64 %0, {%1, %2};" : "=l"(d) : "f"(x), "f"(y));
    return d;
}
__device__ __forceinline__ void cp16(uint32_t dst, const void* src) {
    asm volatile("cp.async.cg.shared.global [%0], [%1], 16;" :: "r"(dst), "l"(src));
}

// ---------- prep 1: verts + |v|^2 as float4 ----------
__global__ void prep_vn_kernel(const float* __restrict__ vertsL,
                               const float* __restrict__ vertsR) {
    const int v  = blockIdx.x * 256 + threadIdx.x;
    const int bs = blockIdx.y;
    const int b = bs >> 1, side = bs & 1;
    const float* vp = (side ? vertsR : vertsL) + ((size_t)b * VV + v) * 3;
    const float x = vp[0], y = vp[1], z = vp[2];
    g_vn[(size_t)bs * VV + v] = make_float4(x, y, z, fmaf(x, x, fmaf(y, y, z * z)));
}

// ---------- prep 2: transpose/pad MLP weights ----------
__global__ void prep_w1_kernel(const float* __restrict__ w1,
                               const float* __restrict__ b1,
                               const float* __restrict__ w2) {
    const int idx = blockIdx.x * 256 + threadIdx.x;
    if (idx < 132 * 132) {
        const int k = idx / 132, j = idx % 132;
        g_w1t[idx] = (j < 130 && k < 130) ? w1[j * 130 + k] : 0.f;
    }
    if (blockIdx.x == 0 && idx < 132) {
        g_b1p[idx] = (idx < 130) ? b1[idx] : 0.f;
        g_w2p[idx] = (idx < 130) ? w2[idx] : 0.f;
    }
}

// ---------- fused RBF interpolation (partial sums) ----------
// grid: (L/128, SS, 2*B); block: 128 threads (4 warps share the verts tile)
__global__ void __launch_bounds__(128, 4) interp_kernel(
    const float* __restrict__ locsL, const float* __restrict__ locsR,
    const float* __restrict__ featsL, const float* __restrict__ featsR) {
    __shared__ __align__(16) float  fs[2][TVC * CC];   // 2 x 16 KB
    __shared__ __align__(16) float4 vs[2][TVC];        // 2 x 1 KB

    const int tid  = threadIdx.x;
    const int lt   = blockIdx.x;
    const int s    = blockIdx.y;
    const int bs   = blockIdx.z;
    const int b = bs >> 1, side = bs & 1;

    const int l = lt * 128 + tid;
    const float* lp = (side ? locsR : locsL) + ((size_t)b * LL + l) * 3;
    const float px = lp[0], py = lp[1], pz = lp[2];
    const float n2 = fmaf(px, px, fmaf(py, py, pz * pz));

    const float*  fbase = (side ? featsR : featsL) + ((size_t)b * VV + s * VSUB) * CC;
    const float4* vbase = g_vn + (size_t)bs * VV + s * VSUB;

    const uint32_t fs_addr = (uint32_t)__cvta_generic_to_shared(&fs[0][0]);
    const uint32_t vs_addr = (uint32_t)__cvta_generic_to_shared(&vs[0][0]);

    unsigned long long acc[32];
#pragma unroll
    for (int i = 0; i < 32; i++) acc[i] = 0ull;
    float dens = 0.f;

#define STAGE(bufi, chunk)                                                      \
    do {                                                                        \
        const float* srcF = fbase + (size_t)(chunk) * (TVC * CC);               \
        const uint32_t fd = fs_addr + (bufi) * (TVC * CC * 4);                  \
        _Pragma("unroll")                                                       \
        for (int i_ = 0; i_ < (TVC * CC / 4 / 128); i_++)                       \
            cp16(fd + (tid + i_ * 128) * 16, srcF + (tid + i_ * 128) * 4);      \
        if (tid < TVC)                                                          \
            cp16(vs_addr + (bufi) * (TVC * 16) + tid * 16,                      \
                 vbase + (size_t)(chunk) * TVC + tid);                          \
        asm volatile("cp.async.commit_group;");                                 \
    } while (0)

    STAGE(0, 0);

    for (int c = 0; c < NCHK; c++) {
        const int buf = c & 1;
        if (c + 1 < NCHK) {
            STAGE(buf ^ 1, c + 1);
            asm volatile("cp.async.wait_group 1;");
        } else {
            asm volatile("cp.async.wait_group 0;");
        }
        __syncthreads();

        const float4* vsp = &vs[buf][0];
        const float*  fsp = &fs[buf][0];
#pragma unroll 2
        for (int j = 0; j < TVC; j++) {
            const float4 vv = vsp[j];
            const float t  = fmaf(px, vv.x, fmaf(py, vv.y, pz * vv.z));
            const float d2 = fmaf(-2.f, t, n2 + vv.w);
            const float d  = sqrtf(fmaxf(d2, 0.f));
            const float w  = __expf(d * -0.4f);      // exp(-d/2.5)
            dens += w;
            const unsigned long long wp = pack2(w, w);
            const ulonglong2* fr = (const ulonglong2*)(fsp + j * CC);
#pragma unroll
            for (int i = 0; i < 8; i++) {
                ulonglong2 q = fr[i];
                acc[2 * i + 0] = fma2(wp, q.x, acc[2 * i + 0]);
                acc[2 * i + 1] = fma2(wp, q.y, acc[2 * i + 1]);
            }
#pragma unroll
            for (int i = 8; i < 16; i++) {
                ulonglong2 q = fr[i];
                acc[2 * i + 0] = fma2(wp, q.x, acc[2 * i + 0]);
                acc[2 * i + 1] = fma2(wp, q.y, acc[2 * i + 1]);
            }
        }
        __syncthreads();
    }
#undef STAGE

    // unnormalized partial sums + dens
    const size_t row = (size_t)s * NQ + (size_t)b * LL + l;
    float* orow = g_part + row * ROWF + side * 64;
    ulonglong2* ov = (ulonglong2*)orow;
#pragma unroll
    for (int i = 0; i < 16; i++) {
        ulonglong2 q; q.x = acc[2 * i]; q.y = acc[2 * i + 1];
        ov[i] = q;
    }
    g_part[row * ROWF + 128 + side] = dens;
}

// ---------- MLP: sum partials, normalize, 130->130 relu ->1 ----------
// block 256 = 8 warps, each warp handles 2 query rows
__global__ void __launch_bounds__(256) mlp_kernel(
    const float* __restrict__ b2, float* __restrict__ out) {
    __shared__ float xs[8][2][132];
    const int warp = threadIdx.x >> 5;
    const int lane = threadIdx.x & 31;
    const int q0 = (blockIdx.x * 8 + warp) * 2;

#pragma unroll
    for (int qq = 0; qq < 2; qq++) {
        const int q = q0 + qq;
        float v[5];
#pragma unroll
        for (int m = 0; m < 5; m++) {
            const int c = lane + 32 * m;
            float sum = 0.f;
            if (c < 130) {
#pragma unroll
                for (int s = 0; s < SS; s++)
                    sum += g_part[((size_t)s * NQ + q) * ROWF + c];
            }
            v[m] = sum;
        }
        const float dl = __shfl_sync(0xFFFFFFFFu, v[4], 0);
        const float dr = __shfl_sync(0xFFFFFFFFu, v[4], 1);
        const float il = 1.f / dl, ir = 1.f / dr;
#pragma unroll
        for (int m = 0; m < 5; m++) {
            const int c = lane + 32 * m;
            if (c < 64)        xs[warp][qq][c] = v[m] * il;
            else if (c < 128)  xs[warp][qq][c + 1] = v[m] * ir;
            else if (c == 128) xs[warp][qq][64] = dl;
            else if (c == 129) xs[warp][qq][129] = dr;
        }
    }
    __syncwarp();

    const float4* wv = (const float4*)g_w1t;   // 33 float4 per k-row
    float4 hA0 = make_float4(0, 0, 0, 0), hA1 = hA0, hB0 = hA0, hB1 = hA0;
#pragma unroll 2
    for (int k = 0; k < 130; k++) {
        const float4 wA = wv[k * 33 + lane];
        const float4 wB = wv[k * 33 + 32];
        const float x0 = xs[warp][0][k];
        const float x1 = xs[warp][1][k];
        hA0.x = fmaf(wA.x, x0, hA0.x); hA0.y = fmaf(wA.y, x0, hA0.y);
        hA0.z = fmaf(wA.z, x0, hA0.z); hA0.w = fmaf(wA.w, x0, hA0.w);
        hA1.x = fmaf(wA.x, x1, hA1.x); hA1.y = fmaf(wA.y, x1, hA1.y);
        hA1.z = fmaf(wA.z, x1, hA1.z); hA1.w = fmaf(wA.w, x1, hA1.w);
        hB0.x = fmaf(wB.x, x0, hB0.x); hB0.y = fmaf(wB.y, x0, hB0.y);
        hB0.z = fmaf(wB.z, x0, hB0.z); hB0.w = fmaf(wB.w, x0, hB0.w);
        hB1.x = fmaf(wB.x, x1, hB1.x); hB1.y = fmaf(wB.y, x1, hB1.y);
        hB1.z = fmaf(wB.z, x1, hB1.z); hB1.w = fmaf(wB.w, x1, hB1.w);
    }

    const float4 b1A = ((const float4*)g_b1p)[lane];
    const float4 w2A = ((const float4*)g_w2p)[lane];
    const float4 b1B = ((const float4*)g_b1p)[32];
    const float4 w2B = ((const float4*)g_w2p)[32];

    float r0 = fmaxf(hA0.x + b1A.x, 0.f) * w2A.x + fmaxf(hA0.y + b1A.y, 0.f) * w2A.y
             + fmaxf(hA0.z + b1A.z, 0.f) * w2A.z + fmaxf(hA0.w + b1A.w, 0.f) * w2A.w;
    float r1 = fmaxf(hA1.x + b1A.x, 0.f) * w2A.x + fmaxf(hA1.y + b1A.y, 0.f) * w2A.y
             + fmaxf(hA1.z + b1A.z, 0.f) * w2A.z + fmaxf(hA1.w + b1A.w, 0.f) * w2A.w;
    if (lane == 0) {
        r0 += fmaxf(hB0.x + b1B.x, 0.f) * w2B.x + fmaxf(hB0.y + b1B.y, 0.f) * w2B.y
            + fmaxf(hB0.z + b1B.z, 0.f) * w2B.z + fmaxf(hB0.w + b1B.w, 0.f) * w2B.w;
        r1 += fmaxf(hB1.x + b1B.x, 0.f) * w2B.x + fmaxf(hB1.y + b1B.y, 0.f) * w2B.y
            + fmaxf(hB1.z + b1B.z, 0.f) * w2B.z + fmaxf(hB1.w + b1B.w, 0.f) * w2B.w;
    }
#pragma unroll
    for (int o = 16; o > 0; o >>= 1) {
        r0 += __shfl_xor_sync(0xFFFFFFFFu, r0, o);
        r1 += __shfl_xor_sync(0xFFFFFFFFu, r1, o);
    }
    if (lane == 0) {
        const float bb = b2[0];
        out[q0 + 0] = r0 + bb;
        out[q0 + 1] = r1 + bb;
    }
}

extern "C" void kernel_launch(void* const* d_in, const int* in_sizes, int n_in,
                              void* d_out, int out_size) {
    (void)in_sizes; (void)n_in; (void)out_size;
    const float* locsL  = (const float*)d_in[0];
    const float* locsR  = (const float*)d_in[1];
    const float* vertsL = (const float*)d_in[2];
    const float* vertsR = (const float*)d_in[3];
    const float* featsL = (const float*)d_in[4];
    const float* featsR = (const float*)d_in[5];
    const float* w1     = (const float*)d_in[6];
    const float* b1     = (const float*)d_in[7];
    const float* w2     = (const float*)d_in[8];
    const float* b2     = (const float*)d_in[9];
    float* out = (float*)d_out;

    prep_vn_kernel<<<dim3(VV / 256, 16), 256>>>(vertsL, vertsR);
    prep_w1_kernel<<<69, 256>>>(w1, b1, w2);
    interp_kernel<<<dim3(LL / 128, SS, 2 * BB), 128>>>(locsL, locsR, featsL, featsR);
    mlp_kernel<<<NQ / 16, 256>>>(b2, out);
}

// round 5
// speedup vs baseline: 2.9679x; 2.9679x over previous
#include <cuda_runtime.h>
#include <cstdint>

#define BB 8
#define LL 2048
#define VV 8192
#define CC 64
#define NQ (BB * LL)
#define NVH 2
#define VH (VV / NVH)        // 4096 verts per CTA
#define NCH (VH / 64)        // 64 chunks of 64 verts
#define RX 136

static __device__ float    g_part[(size_t)NVH * NQ * RX];   // [vh][q][136]
static __device__ float4   g_vn[2 * BB * VV];                // permuted slots
static __device__ uint16_t g_fhT[(size_t)2 * BB * CC * VV];  // bf16 hi, [bs][c][vslot]
static __device__ uint16_t g_flT[(size_t)2 * BB * CC * VV];  // bf16 lo
static __device__ float    g_w1t[132 * 132];
static __device__ float    g_b1p[132];
static __device__ float    g_w2p[132];

// slot permutation within each 16-vert group: perm[s] lists original k;
// inv(k) = storage slot of original k.
__host__ __device__ __forceinline__ int inv16(int k) {
    return ((k >> 1) & 3) * 4 + (k & 1) + ((k >> 3) << 1);
}

__device__ __forceinline__ void cp16(uint32_t d, const void* s) {
    asm volatile("cp.async.cg.shared.global [%0], [%1], 16;" :: "r"(d), "l"(s));
}
__device__ __forceinline__ void lds64(uint32_t& a, uint32_t& b, uint32_t addr) {
    asm volatile("ld.shared.v2.b32 {%0,%1}, [%2];" : "=r"(a), "=r"(b) : "r"(addr));
}
__device__ __forceinline__ void mma16816(float* d, uint32_t a0, uint32_t a1, uint32_t a2,
                                         uint32_t a3, uint32_t b0, uint32_t b1) {
    asm volatile(
        "mma.sync.aligned.m16n8k16.row.col.f32.bf16.bf16.f32 "
        "{%0,%1,%2,%3},{%4,%5,%6,%7},{%8,%9},{%0,%1,%2,%3};"
        : "+f"(d[0]), "+f"(d[1]), "+f"(d[2]), "+f"(d[3])
        : "r"(a0), "r"(a1), "r"(a2), "r"(a3), "r"(b0), "r"(b1));
}

// ---------------- preps ----------------
__global__ void prep_vn_kernel(const float* __restrict__ vL, const float* __restrict__ vR) {
    const int v = blockIdx.x * 256 + threadIdx.x;
    const int bs = blockIdx.y, b = bs >> 1, side = bs & 1;
    const float* vp = (side ? vR : vL) + ((size_t)b * VV + v) * 3;
    const float x = vp[0], y = vp[1], z = vp[2];
    const int vs = (v & ~15) | inv16(v & 15);
    g_vn[(size_t)bs * VV + vs] = make_float4(x, y, z, fmaf(x, x, fmaf(y, y, z * z)));
}

__global__ void prep_feats_kernel(const float* __restrict__ fL, const float* __restrict__ fR) {
    __shared__ float tile[64][65];
    const int vt = blockIdx.x, bs = blockIdx.y, b = bs >> 1, side = bs & 1;
    const int tid = threadIdx.x;
    const float* src = (side ? fR : fL) + ((size_t)b * VV + (size_t)vt * 64) * CC;
#pragma unroll
    for (int i = 0; i < 16; i++) {
        int idx = tid + 256 * i;
        tile[idx >> 6][idx & 63] = src[idx];
    }
    __syncthreads();
#pragma unroll
    for (int i = 0; i < 16; i++) {
        int idx = tid + 256 * i;
        int c = idx >> 6, v = idx & 63;
        float f = tile[v][c];
        uint32_t u = __float_as_uint(f);
        float lo = f - __uint_as_float(u & 0xFFFF0000u);
        int vs = (v & ~15) | inv16(v & 15);
        size_t off = ((size_t)bs * CC + c) * VV + (size_t)vt * 64 + vs;
        g_fhT[off] = (uint16_t)(u >> 16);
        g_flT[off] = (uint16_t)(__float_as_uint(lo) >> 16);
    }
}

__global__ void prep_w1_kernel(const float* __restrict__ w1, const float* __restrict__ b1,
                               const float* __restrict__ w2) {
    const int idx = blockIdx.x * 256 + threadIdx.x;
    if (idx < 132 * 132) {
        const int k = idx / 132, j = idx % 132;
        g_w1t[idx] = (j < 130 && k < 130) ? w1[j * 130 + k] : 0.f;
    }
    if (blockIdx.x == 0 && idx < 132) {
        g_b1p[idx] = (idx < 130) ? b1[idx] : 0.f;
        g_w2p[idx] = (idx < 130) ? w2[idx] : 0.f;
    }
}

// ---------------- fused interp: W-gen in regs + mma.sync bf16x3 ----------------
// grid (LL/128, 16, NVH), block 128 (4 warps, each M=32 x N=64)
#define STG 17408            // per-stage smem bytes: fh 8K + fl 8K + vn 1K + pad

__global__ void __launch_bounds__(128, 3)
interp_kernel(const float* __restrict__ locsL, const float* __restrict__ locsR) {
    __shared__ __align__(1024) char smem[2 * STG];
    const uint32_t sb = (uint32_t)__cvta_generic_to_shared(smem);
    const int tid = threadIdx.x, lane = tid & 31, warp = tid >> 5;
    const int lt = blockIdx.x, bs = blockIdx.y, vh = blockIdx.z;
    const int b = bs >> 1, side = bs & 1;
    const int wm = warp * 32;
    const int voff = vh * VH;

    const float* locs = (side ? locsR : locsL) + (size_t)b * LL * 3;
    float px[4], py[4], pz[4], n2[4], dens[4];
    const int rbase = lt * 128 + wm + (lane >> 2);
#pragma unroll
    for (int ri = 0; ri < 4; ri++) {
        const float* p = locs + (size_t)(rbase + ri * 8) * 3;
        px[ri] = p[0]; py[ri] = p[1]; pz[ri] = p[2];
        n2[ri] = fmaf(px[ri], px[ri], fmaf(py[ri], py[ri], pz[ri] * pz[ri]));
        dens[ri] = 0.f;
    }
    const uint16_t* fhb = g_fhT + (size_t)bs * CC * VV + voff;
    const uint16_t* flb = g_flT + (size_t)bs * CC * VV + voff;
    const float4*   vnb = g_vn + (size_t)bs * VV + voff;

    float acc[2][8][4];
#pragma unroll
    for (int m = 0; m < 2; m++)
#pragma unroll
        for (int t = 0; t < 8; t++)
#pragma unroll
            for (int i = 0; i < 4; i++) acc[m][t][i] = 0.f;

    auto stage_cp = [&](int ch) {
        const uint32_t dst = sb + (uint32_t)(ch & 1) * STG;
#pragma unroll
        for (int i = 0; i < 4; i++) {                 // fh: 512 units
            int idx = tid + i * 128;
            int c = idx >> 3, u = idx & 7;
            cp16(dst + c * 128 + ((u * 16) ^ ((c & 7) * 16)),
                 fhb + (size_t)c * VV + ch * 64 + u * 8);
        }
#pragma unroll
        for (int i = 0; i < 4; i++) {                 // fl: 512 units
            int idx = tid + i * 128;
            int c = idx >> 3, u = idx & 7;
            cp16(dst + 8192 + c * 128 + ((u * 16) ^ ((c & 7) * 16)),
                 flb + (size_t)c * VV + ch * 64 + u * 8);
        }
        if (tid < 64) cp16(dst + 16384 + tid * 16, vnb + ch * 64 + tid);
        asm volatile("cp.async.commit_group;");
    };

    stage_cp(0);
    stage_cp(1);

    const uint32_t bswz = (uint32_t)((lane >> 2) << 4);
    const uint32_t koff = (uint32_t)((lane & 3) * 8);

    for (int ch = 0; ch < NCH; ch++) {
        const int s = ch & 1;
        if (ch == NCH - 1) asm volatile("cp.async.wait_group 0;");
        else               asm volatile("cp.async.wait_group 1;");
        __syncthreads();

        const uint32_t fbase = sb + (uint32_t)s * STG;
        const float4* vns = (const float4*)(smem + (size_t)s * STG + 16384);

#pragma unroll 1
        for (int kk = 0; kk < 4; kk++) {
            float4 vq[4];
#pragma unroll
            for (int j = 0; j < 4; j++) vq[j] = vns[kk * 16 + (lane & 3) * 4 + j];

            uint32_t HI[4][2], LO[4][2];
#pragma unroll
            for (int ri = 0; ri < 4; ri++) {
                float w[4];
#pragma unroll
                for (int j = 0; j < 4; j++) {
                    float t  = fmaf(px[ri], vq[j].x, fmaf(py[ri], vq[j].y, pz[ri] * vq[j].z));
                    float d2 = fmaxf(fmaf(-2.f, t, n2[ri] + vq[j].w), 0.f);
                    float d; asm("sqrt.approx.f32 %0,%1;" : "=f"(d) : "f"(d2));
                    float e; asm("ex2.approx.f32 %0,%1;" : "=f"(e) : "f"(d * -0.57707801635558535f));
                    w[j] = e; dens[ri] += e;
                }
                uint32_t u0 = __float_as_uint(w[0]), u1 = __float_as_uint(w[1]);
                uint32_t u2 = __float_as_uint(w[2]), u3 = __float_as_uint(w[3]);
                HI[ri][0] = __byte_perm(u0, u1, 0x7632);
                HI[ri][1] = __byte_perm(u2, u3, 0x7632);
                float l0 = w[0] - __uint_as_float(u0 & 0xFFFF0000u);
                float l1 = w[1] - __uint_as_float(u1 & 0xFFFF0000u);
                float l2 = w[2] - __uint_as_float(u2 & 0xFFFF0000u);
                float l3 = w[3] - __uint_as_float(u3 & 0xFFFF0000u);
                LO[ri][0] = __byte_perm(__float_as_uint(l0), __float_as_uint(l1), 0x7632);
                LO[ri][1] = __byte_perm(__float_as_uint(l2), __float_as_uint(l3), 0x7632);
            }

            const uint32_t kb = (uint32_t)(kk * 32 + koff) ^ bswz;
#pragma unroll
            for (int t = 0; t < 8; t++) {
                const uint32_t addr = fbase + (uint32_t)((t * 8 + (lane >> 2)) * 128) + kb;
                uint32_t bh0, bh1, bl0, bl1;
                lds64(bh0, bh1, addr);
                lds64(bl0, bl1, addr + 8192);
                mma16816(acc[0][t], HI[0][0], HI[1][0], HI[0][1], HI[1][1], bh0, bh1);
                mma16816(acc[0][t], HI[0][0], HI[1][0], HI[0][1], HI[1][1], bl0, bl1);
                mma16816(acc[0][t], LO[0][0], LO[1][0], LO[0][1], LO[1][1], bh0, bh1);
                mma16816(acc[1][t], HI[2][0], HI[3][0], HI[2][1], HI[3][1], bh0, bh1);
                mma16816(acc[1][t], HI[2][0], HI[3][0], HI[2][1], HI[3][1], bl0, bl1);
                mma16816(acc[1][t], LO[2][0], LO[3][0], LO[2][1], LO[3][1], bh0, bh1);
            }
        }
        __syncthreads();
        if (ch + 2 < NCH) stage_cp(ch + 2);
    }

    // dens reduce across the 4 lanes sharing a row
#pragma unroll
    for (int ri = 0; ri < 4; ri++) {
        dens[ri] += __shfl_xor_sync(0xFFFFFFFFu, dens[ri], 1);
        dens[ri] += __shfl_xor_sync(0xFFFFFFFFu, dens[ri], 2);
    }

    // write unnormalized partials + dens
#pragma unroll
    for (int ri = 0; ri < 4; ri++) {
        const size_t q = (size_t)b * LL + rbase + ri * 8;
        float* orow = g_part + ((size_t)vh * NQ + q) * RX + side * 68;
        const int mt = ri >> 1, rp = (ri & 1) * 2;
#pragma unroll
        for (int t = 0; t < 8; t++) {
            float2 v2;
            v2.x = acc[mt][t][rp + 0];
            v2.y = acc[mt][t][rp + 1];
            *(float2*)(orow + t * 8 + (lane & 3) * 2) = v2;
        }
        if ((lane & 3) == 0) orow[64] = dens[ri];
    }
}

// ---------------- MLP: combine halves, normalize, 130->130 relu ->1 ----------------
__global__ void __launch_bounds__(256) mlp_kernel(const float* __restrict__ b2,
                                                  float* __restrict__ out) {
    __shared__ float xs[8][4][132];
    const int warp = threadIdx.x >> 5;
    const int lane = threadIdx.x & 31;
    const int q0 = (blockIdx.x * 8 + warp) * 4;

#pragma unroll
    for (int qq = 0; qq < 4; qq++) {
        const size_t q = q0 + qq;
        const float* r0 = g_part + q * RX;
        const float* r1 = g_part + ((size_t)NQ + q) * RX;
        float v[5];
#pragma unroll
        for (int m = 0; m < 5; m++) {
            const int c = lane + 32 * m;
            if (c < 130) {
                const int pc = c < 65 ? c : c + 3;
                v[m] = r0[pc] + r1[pc];
            } else v[m] = 0.f;
        }
        const float dl = __shfl_sync(0xFFFFFFFFu, v[2], 0);
        const float dr = __shfl_sync(0xFFFFFFFFu, v[4], 1);
        const float il = 1.f / dl, ir = 1.f / dr;
#pragma unroll
        for (int m = 0; m < 5; m++) {
            const int c = lane + 32 * m;
            if (c < 64)        xs[warp][qq][c] = v[m] * il;
            else if (c == 64)  xs[warp][qq][64] = dl;
            else if (c < 129)  xs[warp][qq][c] = v[m] * ir;
            else if (c == 129) xs[warp][qq][129] = dr;
        }
    }
    __syncwarp();

    const float4* wv = (const float4*)g_w1t;
    float4 hA[4], hB[4];
#pragma unroll
    for (int qq = 0; qq < 4; qq++) { hA[qq] = make_float4(0, 0, 0, 0); hB[qq] = hA[qq]; }
#pragma unroll 2
    for (int k = 0; k < 130; k++) {
        const float4 wA = wv[k * 33 + lane];
        const float4 wB = wv[k * 33 + 32];
#pragma unroll
        for (int qq = 0; qq < 4; qq++) {
            const float x = xs[warp][qq][k];
            hA[qq].x = fmaf(wA.x, x, hA[qq].x); hA[qq].y = fmaf(wA.y, x, hA[qq].y);
            hA[qq].z = fmaf(wA.z, x, hA[qq].z); hA[qq].w = fmaf(wA.w, x, hA[qq].w);
            hB[qq].x = fmaf(wB.x, x, hB[qq].x); hB[qq].y = fmaf(wB.y, x, hB[qq].y);
            hB[qq].z = fmaf(wB.z, x, hB[qq].z); hB[qq].w = fmaf(wB.w, x, hB[qq].w);
        }
    }
    const float4 b1A = ((const float4*)g_b1p)[lane];
    const float4 w2A = ((const float4*)g_w2p)[lane];
    const float4 b1B = ((const float4*)g_b1p)[32];
    const float4 w2B = ((const float4*)g_w2p)[32];
    const float bb = b2[0];

#pragma unroll
    for (int qq = 0; qq < 4; qq++) {
        float r = fmaxf(hA[qq].x + b1A.x, 0.f) * w2A.x + fmaxf(hA[qq].y + b1A.y, 0.f) * w2A.y
                + fmaxf(hA[qq].z + b1A.z, 0.f) * w2A.z + fmaxf(hA[qq].w + b1A.w, 0.f) * w2A.w;
        if (lane == 0)
            r += fmaxf(hB[qq].x + b1B.x, 0.f) * w2B.x + fmaxf(hB[qq].y + b1B.y, 0.f) * w2B.y
               + fmaxf(hB[qq].z + b1B.z, 0.f) * w2B.z + fmaxf(hB[qq].w + b1B.w, 0.f) * w2B.w;
#pragma unroll
        for (int o = 16; o > 0; o >>= 1) r += __shfl_xor_sync(0xFFFFFFFFu, r, o);
        if (lane == 0) out[q0 + qq] = r + bb;
    }
}

extern "C" void kernel_launch(void* const* d_in, const int* in_sizes, int n_in,
                              void* d_out, int out_size) {
    (void)in_sizes; (void)n_in; (void)out_size;
    const float* locsL  = (const float*)d_in[0];
    const float* locsR  = (const float*)d_in[1];
    const float* vertsL = (const float*)d_in[2];
    const float* vertsR = (const float*)d_in[3];
    const float* featsL = (const float*)d_in[4];
    const float* featsR = (const float*)d_in[5];
    const float* w1     = (const float*)d_in[6];
    const float* b1     = (const float*)d_in[7];
    const float* w2     = (const float*)d_in[8];
    const float* b2     = (const float*)d_in[9];
    float* out = (float*)d_out;

    prep_vn_kernel<<<dim3(VV / 256, 16), 256>>>(vertsL, vertsR);
    prep_feats_kernel<<<dim3(VV / 64, 16), 256>>>(featsL, featsR);
    prep_w1_kernel<<<69, 256>>>(w1, b1, w2);
    interp_kernel<<<dim3(LL / 128, 16, NVH), 128>>>(locsL, locsR);
    mlp_kernel<<<NQ / 32, 256>>>(b2, out);
}

// round 6
// speedup vs baseline: 4.0956x; 1.3800x over previous
#include <cuda_runtime.h>
#include <cuda_fp16.h>
#include <cstdint>

#define BB 8
#define LL 2048
#define VV 8192
#define CC 64
#define NQ (BB * LL)
#define NVH 8
#define VH (VV / NVH)        // 1024 verts per CTA
#define NCH (VH / 64)        // 16 chunks of 64 verts
#define RX 136

static __device__ float    g_part[(size_t)NVH * NQ * RX];   // [vh][q][136]
static __device__ float4   g_vn[2 * BB * VV];                // permuted slots
static __device__ uint16_t g_fhT[(size_t)2 * BB * CC * VV];  // fp16 hi, [bs][c][vslot]
static __device__ uint16_t g_flT[(size_t)2 * BB * CC * VV];  // fp16 lo
static __device__ float    g_w1t[132 * 132];
static __device__ float    g_b1p[132];
static __device__ float    g_w2p[132];

// slot permutation within each 16-vert group (k-major mma B fragment via lds64)
__host__ __device__ __forceinline__ int inv16(int k) {
    return ((k >> 1) & 3) * 4 + (k & 1) + ((k >> 3) << 1);
}

__device__ __forceinline__ void cp16(uint32_t d, const void* s) {
    asm volatile("cp.async.cg.shared.global [%0], [%1], 16;" :: "r"(d), "l"(s));
}
__device__ __forceinline__ void lds64(uint32_t& a, uint32_t& b, uint32_t addr) {
    asm volatile("ld.shared.v2.b32 {%0,%1}, [%2];" : "=r"(a), "=r"(b) : "r"(addr));
}
__device__ __forceinline__ uint32_t packh2(float lo, float hi) {
    uint32_t r;
    asm("cvt.rn.f16x2.f32 %0, %1, %2;" : "=r"(r) : "f"(hi), "f"(lo));
    return r;
}
__device__ __forceinline__ void mma16816(float* d, uint32_t a0, uint32_t a1, uint32_t a2,
                                         uint32_t a3, uint32_t b0, uint32_t b1) {
    asm volatile(
        "mma.sync.aligned.m16n8k16.row.col.f32.f16.f16.f32 "
        "{%0,%1,%2,%3},{%4,%5,%6,%7},{%8,%9},{%0,%1,%2,%3};"
        : "+f"(d[0]), "+f"(d[1]), "+f"(d[2]), "+f"(d[3])
        : "r"(a0), "r"(a1), "r"(a2), "r"(a3), "r"(b0), "r"(b1));
}

// ---------------- preps ----------------
__global__ void prep_vn_kernel(const float* __restrict__ vL, const float* __restrict__ vR) {
    const int v = blockIdx.x * 256 + threadIdx.x;
    const int bs = blockIdx.y, b = bs >> 1, side = bs & 1;
    const float* vp = (side ? vR : vL) + ((size_t)b * VV + v) * 3;
    const float x = vp[0], y = vp[1], z = vp[2];
    const int vs = (v & ~15) | inv16(v & 15);
    g_vn[(size_t)bs * VV + vs] = make_float4(x, y, z, fmaf(x, x, fmaf(y, y, z * z)));
}

__global__ void prep_feats_kernel(const float* __restrict__ fL, const float* __restrict__ fR) {
    __shared__ float tile[64][65];
    const int vt = blockIdx.x, bs = blockIdx.y, b = bs >> 1, side = bs & 1;
    const int tid = threadIdx.x;
    const float* src = (side ? fR : fL) + ((size_t)b * VV + (size_t)vt * 64) * CC;
#pragma unroll
    for (int i = 0; i < 16; i++) {
        int idx = tid + 256 * i;
        tile[idx >> 6][idx & 63] = src[idx];
    }
    __syncthreads();
#pragma unroll
    for (int i = 0; i < 16; i++) {
        int idx = tid + 256 * i;
        int c = idx >> 6, v = idx & 63;
        float f = tile[v][c];
        __half hh = __float2half_rn(f);
        __half hl = __float2half_rn(f - __half2float(hh));
        int vs = (v & ~15) | inv16(v & 15);
        size_t off = ((size_t)bs * CC + c) * VV + (size_t)vt * 64 + vs;
        g_fhT[off] = __half_as_ushort(hh);
        g_flT[off] = __half_as_ushort(hl);
    }
}

__global__ void prep_w1_kernel(const float* __restrict__ w1, const float* __restrict__ b1,
                               const float* __restrict__ w2) {
    const int idx = blockIdx.x * 256 + threadIdx.x;
    if (idx < 132 * 132) {
        const int k = idx / 132, j = idx % 132;
        g_w1t[idx] = (j < 130 && k < 130) ? w1[j * 130 + k] : 0.f;
    }
    if (blockIdx.x == 0 && idx < 132) {
        g_b1p[idx] = (idx < 130) ? b1[idx] : 0.f;
        g_w2p[idx] = (idx < 130) ? w2[idx] : 0.f;
    }
}

// ---------------- fused interp: W-gen in regs + mma.sync fp16 2-pass ----------------
// grid (LL/128, 16, NVH), block 128 (4 warps, each M=32 x N=64)
#define STG 17408            // per-stage smem bytes: fh 8K + fl 8K + vn 1K + pad

__global__ void __launch_bounds__(128, 3)
interp_kernel(const float* __restrict__ locsL, const float* __restrict__ locsR) {
    __shared__ __align__(1024) char smem[2 * STG];
    const uint32_t sb = (uint32_t)__cvta_generic_to_shared(smem);
    const int tid = threadIdx.x, lane = tid & 31, warp = tid >> 5;
    const int lt = blockIdx.x, bs = blockIdx.y, vh = blockIdx.z;
    const int b = bs >> 1, side = bs & 1;
    const int voff = vh * VH;

    const float* locs = (side ? locsR : locsL) + (size_t)b * LL * 3;
    float px[4], py[4], pz[4], n2[4], dens[4];
    const int rbase = lt * 128 + warp * 32 + (lane >> 2);
#pragma unroll
    for (int ri = 0; ri < 4; ri++) {
        const float* p = locs + (size_t)(rbase + ri * 8) * 3;
        px[ri] = p[0]; py[ri] = p[1]; pz[ri] = p[2];
        n2[ri] = fmaf(px[ri], px[ri], fmaf(py[ri], py[ri], pz[ri] * pz[ri]));
        dens[ri] = 0.f;
    }
    const uint16_t* fhb = g_fhT + (size_t)bs * CC * VV + voff;
    const uint16_t* flb = g_flT + (size_t)bs * CC * VV + voff;
    const float4*   vnb = g_vn + (size_t)bs * VV + voff;

    float acc[2][8][4];
#pragma unroll
    for (int m = 0; m < 2; m++)
#pragma unroll
        for (int t = 0; t < 8; t++)
#pragma unroll
            for (int i = 0; i < 4; i++) acc[m][t][i] = 0.f;

    auto stage_cp = [&](int ch) {
        const uint32_t dst = sb + (uint32_t)(ch & 1) * STG;
#pragma unroll
        for (int i = 0; i < 4; i++) {
            int idx = tid + i * 128;
            int c = idx >> 3, u = idx & 7;
            cp16(dst + c * 128 + ((u * 16) ^ ((c & 7) * 16)),
                 fhb + (size_t)c * VV + ch * 64 + u * 8);
        }
#pragma unroll
        for (int i = 0; i < 4; i++) {
            int idx = tid + i * 128;
            int c = idx >> 3, u = idx & 7;
            cp16(dst + 8192 + c * 128 + ((u * 16) ^ ((c & 7) * 16)),
                 flb + (size_t)c * VV + ch * 64 + u * 8);
        }
        if (tid < 64) cp16(dst + 16384 + tid * 16, vnb + ch * 64 + tid);
        asm volatile("cp.async.commit_group;");
    };

    stage_cp(0);
    stage_cp(1);

    const uint32_t bswz = (uint32_t)((lane >> 2) << 4);
    const uint32_t koff = (uint32_t)((lane & 3) * 8);

    for (int ch = 0; ch < NCH; ch++) {
        const int s = ch & 1;
        if (ch == NCH - 1) asm volatile("cp.async.wait_group 0;");
        else               asm volatile("cp.async.wait_group 1;");
        __syncthreads();

        const uint32_t fbase = sb + (uint32_t)s * STG;
        const float4* vns = (const float4*)(smem + (size_t)s * STG + 16384);

#pragma unroll 1
        for (int kk = 0; kk < 4; kk++) {
            float4 vq[4];
#pragma unroll
            for (int j = 0; j < 4; j++) vq[j] = vns[kk * 16 + (lane & 3) * 4 + j];

            uint32_t HI[4][2];
#pragma unroll
            for (int ri = 0; ri < 4; ri++) {
                float w[4];
#pragma unroll
                for (int j = 0; j < 4; j++) {
                    float t  = fmaf(px[ri], vq[j].x, fmaf(py[ri], vq[j].y, pz[ri] * vq[j].z));
                    float d2 = fmaxf(fmaf(-2.f, t, n2[ri] + vq[j].w), 0.f);
                    float d; asm("sqrt.approx.f32 %0,%1;" : "=f"(d) : "f"(d2));
                    float e; asm("ex2.approx.f32 %0,%1;" : "=f"(e) : "f"(d * -0.57707801635558535f));
                    w[j] = e; dens[ri] += e;
                }
                HI[ri][0] = packh2(w[0], w[1]);
                HI[ri][1] = packh2(w[2], w[3]);
            }

            const uint32_t kb = (uint32_t)(kk * 32 + koff) ^ bswz;
#pragma unroll
            for (int t = 0; t < 8; t++) {
                const uint32_t addr = fbase + (uint32_t)((t * 8 + (lane >> 2)) * 128) + kb;
                uint32_t bh0, bh1, bl0, bl1;
                lds64(bh0, bh1, addr);
                lds64(bl0, bl1, addr + 8192);
                mma16816(acc[0][t], HI[0][0], HI[1][0], HI[0][1], HI[1][1], bh0, bh1);
                mma16816(acc[0][t], HI[0][0], HI[1][0], HI[0][1], HI[1][1], bl0, bl1);
                mma16816(acc[1][t], HI[2][0], HI[3][0], HI[2][1], HI[3][1], bh0, bh1);
                mma16816(acc[1][t], HI[2][0], HI[3][0], HI[2][1], HI[3][1], bl0, bl1);
            }
        }
        __syncthreads();
        if (ch + 2 < NCH) stage_cp(ch + 2);
    }

#pragma unroll
    for (int ri = 0; ri < 4; ri++) {
        dens[ri] += __shfl_xor_sync(0xFFFFFFFFu, dens[ri], 1);
        dens[ri] += __shfl_xor_sync(0xFFFFFFFFu, dens[ri], 2);
    }

#pragma unroll
    for (int ri = 0; ri < 4; ri++) {
        const size_t q = (size_t)b * LL + rbase + ri * 8;
        float* orow = g_part + ((size_t)vh * NQ + q) * RX + side * 68;
        const int mt = ri >> 1, rp = (ri & 1) * 2;
#pragma unroll
        for (int t = 0; t < 8; t++) {
            float2 v2;
            v2.x = acc[mt][t][rp + 0];
            v2.y = acc[mt][t][rp + 1];
            *(float2*)(orow + t * 8 + (lane & 3) * 2) = v2;
        }
        if ((lane & 3) == 0) orow[64] = dens[ri];
    }
}

// ---------------- MLP: combine partials, normalize, 130->130 relu ->1 ----------------
__global__ void __launch_bounds__(256) mlp_kernel(const float* __restrict__ b2,
                                                  float* __restrict__ out) {
    __shared__ float xs[8][4][132];
    const int warp = threadIdx.x >> 5;
    const int lane = threadIdx.x & 31;
    const int q0 = (blockIdx.x * 8 + warp) * 4;

#pragma unroll
    for (int qq = 0; qq < 4; qq++) {
        const size_t q = q0 + qq;
        float v[5];
#pragma unroll
        for (int m = 0; m < 5; m++) {
            const int c = lane + 32 * m;
            float sum = 0.f;
            if (c < 130) {
                const int pc = c < 65 ? c : c + 3;
#pragma unroll
                for (int s = 0; s < NVH; s++)
                    sum += g_part[((size_t)s * NQ + q) * RX + pc];
            }
            v[m] = sum;
        }
        const float dl = __shfl_sync(0xFFFFFFFFu, v[2], 0);
        const float dr = __shfl_sync(0xFFFFFFFFu, v[4], 1);
        const float il = 1.f / dl, ir = 1.f / dr;
#pragma unroll
        for (int m = 0; m < 5; m++) {
            const int c = lane + 32 * m;
            if (c < 64)        xs[warp][qq][c] = v[m] * il;
            else if (c == 64)  xs[warp][qq][64] = dl;
            else if (c < 129)  xs[warp][qq][c] = v[m] * ir;
            else if (c == 129) xs[warp][qq][129] = dr;
        }
    }
    __syncwarp();

    const float4* wv = (const float4*)g_w1t;
    float4 hA[4], hB[4];
#pragma unroll
    for (int qq = 0; qq < 4; qq++) { hA[qq] = make_float4(0, 0, 0, 0); hB[qq] = hA[qq]; }
#pragma unroll 2
    for (int k = 0; k < 130; k++) {
        const float4 wA = wv[k * 33 + lane];
        const float4 wB = wv[k * 33 + 32];
#pragma unroll
        for (int qq = 0; qq < 4; qq++) {
            const float x = xs[warp][qq][k];
            hA[qq].x = fmaf(wA.x, x, hA[qq].x); hA[qq].y = fmaf(wA.y, x, hA[qq].y);
            hA[qq].z = fmaf(wA.z, x, hA[qq].z); hA[qq].w = fmaf(wA.w, x, hA[qq].w);
            hB[qq].x = fmaf(wB.x, x, hB[qq].x); hB[qq].y = fmaf(wB.y, x, hB[qq].y);
            hB[qq].z = fmaf(wB.z, x, hB[qq].z); hB[qq].w = fmaf(wB.w, x, hB[qq].w);
        }
    }
    const float4 b1A = ((const float4*)g_b1p)[lane];
    const float4 w2A = ((const float4*)g_w2p)[lane];
    const float4 b1B = ((const float4*)g_b1p)[32];
    const float4 w2B = ((const float4*)g_w2p)[32];
    const float bb = b2[0];

#pragma unroll
    for (int qq = 0; qq < 4; qq++) {
        float r = fmaxf(hA[qq].x + b1A.x, 0.f) * w2A.x + fmaxf(hA[qq].y + b1A.y, 0.f) * w2A.y
                + fmaxf(hA[qq].z + b1A.z, 0.f) * w2A.z + fmaxf(hA[qq].w + b1A.w, 0.f) * w2A.w;
        if (lane == 0)
            r += fmaxf(hB[qq].x + b1B.x, 0.f) * w2B.x + fmaxf(hB[qq].y + b1B.y, 0.f) * w2B.y
               + fmaxf(hB[qq].z + b1B.z, 0.f) * w2B.z + fmaxf(hB[qq].w + b1B.w, 0.f) * w2B.w;
#pragma unroll
        for (int o = 16; o > 0; o >>= 1) r += __shfl_xor_sync(0xFFFFFFFFu, r, o);
        if (lane == 0) out[q0 + qq] = r + bb;
    }
}

extern "C" void kernel_launch(void* const* d_in, const int* in_sizes, int n_in,
                              void* d_out, int out_size) {
    (void)in_sizes; (void)n_in; (void)out_size;
    const float* locsL  = (const float*)d_in[0];
    const float* locsR  = (const float*)d_in[1];
    const float* vertsL = (const float*)d_in[2];
    const float* vertsR = (const float*)d_in[3];
    const float* featsL = (const float*)d_in[4];
    const float* featsR = (const float*)d_in[5];
    const float* w1     = (const float*)d_in[6];
    const float* b1     = (const float*)d_in[7];
    const float* w2     = (const float*)d_in[8];
    const float* b2     = (const float*)d_in[9];
    float* out = (float*)d_out;

    prep_vn_kernel<<<dim3(VV / 256, 16), 256>>>(vertsL, vertsR);
    prep_feats_kernel<<<dim3(VV / 64, 16), 256>>>(featsL, featsR);
    prep_w1_kernel<<<69, 256>>>(w1, b1, w2);
    interp_kernel<<<dim3(LL / 128, 16, NVH), 128>>>(locsL, locsR);
    mlp_kernel<<<NQ / 32, 256>>>(b2, out);
}

// round 7
// speedup vs baseline: 4.8894x; 1.1938x over previous
#include <cuda_runtime.h>
#include <cuda_fp16.h>
#include <cstdint>

#define BB 8
#define LL 2048
#define VV 8192
#define CC 64
#define NQ (BB * LL)
#define NVH 8
#define VH (VV / NVH)        // 1024 verts per CTA
#define NCH (VH / 64)        // 16 chunks of 64 verts
#define RX 136

static __device__ float    g_part[(size_t)NVH * NQ * RX];   // [vh][q][136]
static __device__ float4   g_vn[2 * BB * VV];                // permuted slots
static __device__ uint16_t g_fhT[(size_t)2 * BB * CC * VV];  // fp16 feats^T, [bs][c][vslot]
static __device__ float    g_w1t[132 * 132];
static __device__ float    g_b1p[132];
static __device__ float    g_w2p[132];

// slot permutation within each 16-vert group (k-major mma B fragment via lds64)
__host__ __device__ __forceinline__ int inv16(int k) {
    return ((k >> 1) & 3) * 4 + (k & 1) + ((k >> 3) << 1);
}

__device__ __forceinline__ void cp16(uint32_t d, const void* s) {
    asm volatile("cp.async.cg.shared.global [%0], [%1], 16;" :: "r"(d), "l"(s));
}
__device__ __forceinline__ void lds64(uint32_t& a, uint32_t& b, uint32_t addr) {
    asm volatile("ld.shared.v2.b32 {%0,%1}, [%2];" : "=r"(a), "=r"(b) : "r"(addr));
}
__device__ __forceinline__ uint32_t packh2(float lo, float hi) {
    uint32_t r;
    asm("cvt.rn.f16x2.f32 %0, %1, %2;" : "=r"(r) : "f"(hi), "f"(lo));
    return r;
}
__device__ __forceinline__ void mma16816(float* d, uint32_t a0, uint32_t a1, uint32_t a2,
                                         uint32_t a3, uint32_t b0, uint32_t b1) {
    asm volatile(
        "mma.sync.aligned.m16n8k16.row.col.f32.f16.f16.f32 "
        "{%0,%1,%2,%3},{%4,%5,%6,%7},{%8,%9},{%0,%1,%2,%3};"
        : "+f"(d[0]), "+f"(d[1]), "+f"(d[2]), "+f"(d[3])
        : "r"(a0), "r"(a1), "r"(a2), "r"(a3), "r"(b0), "r"(b1));
}

// ---------------- preps ----------------
__global__ void prep_vn_kernel(const float* __restrict__ vL, const float* __restrict__ vR) {
    const int v = blockIdx.x * 256 + threadIdx.x;
    const int bs = blockIdx.y, b = bs >> 1, side = bs & 1;
    const float* vp = (side ? vR : vL) + ((size_t)b * VV + v) * 3;
    const float x = vp[0], y = vp[1], z = vp[2];
    const int vs = (v & ~15) | inv16(v & 15);
    g_vn[(size_t)bs * VV + vs] = make_float4(x, y, z, fmaf(x, x, fmaf(y, y, z * z)));
}

__global__ void prep_feats_kernel(const float* __restrict__ fL, const float* __restrict__ fR) {
    __shared__ float tile[64][65];
    const int vt = blockIdx.x, bs = blockIdx.y, b = bs >> 1, side = bs & 1;
    const int tid = threadIdx.x;
    const float* src = (side ? fR : fL) + ((size_t)b * VV + (size_t)vt * 64) * CC;
#pragma unroll
    for (int i = 0; i < 16; i++) {
        int idx = tid + 256 * i;
        tile[idx >> 6][idx & 63] = src[idx];
    }
    __syncthreads();
#pragma unroll
    for (int i = 0; i < 16; i++) {
        int idx = tid + 256 * i;
        int c = idx >> 6, v = idx & 63;
        int vs = (v & ~15) | inv16(v & 15);
        g_fhT[((size_t)bs * CC + c) * VV + (size_t)vt * 64 + vs] =
            __half_as_ushort(__float2half_rn(tile[v][c]));
    }
}

__global__ void prep_w1_kernel(const float* __restrict__ w1, const float* __restrict__ b1,
                               const float* __restrict__ w2) {
    const int idx = blockIdx.x * 256 + threadIdx.x;
    if (idx < 132 * 132) {
        const int k = idx / 132, j = idx % 132;
        g_w1t[idx] = (j < 130 && k < 130) ? w1[j * 130 + k] : 0.f;
    }
    if (blockIdx.x == 0 && idx < 132) {
        g_b1p[idx] = (idx < 130) ? b1[idx] : 0.f;
        g_w2p[idx] = (idx < 130) ? w2[idx] : 0.f;
    }
}

// ---------------- fused interp: W-gen in regs + mma.sync fp16 single-pass ----------------
// grid (LL/128, 16, NVH), block 128 (4 warps, each M=32 x N=64)
#define STG 10240            // per-stage smem: fh 8K @0, vn 1K @8192, pad

__global__ void __launch_bounds__(128, 4)
interp_kernel(const float* __restrict__ locsL, const float* __restrict__ locsR) {
    __shared__ __align__(1024) char smem[2 * STG];
    const uint32_t sb = (uint32_t)__cvta_generic_to_shared(smem);
    const int tid = threadIdx.x, lane = tid & 31, warp = tid >> 5;
    const int lt = blockIdx.x, bs = blockIdx.y, vh = blockIdx.z;
    const int b = bs >> 1, side = bs & 1;
    const int voff = vh * VH;

    const float* locs = (side ? locsR : locsL) + (size_t)b * LL * 3;
    float px[4], py[4], pz[4], n2[4], dens[4];
    const int rbase = lt * 128 + warp * 32 + (lane >> 2);
#pragma unroll
    for (int ri = 0; ri < 4; ri++) {
        const float* p = locs + (size_t)(rbase + ri * 8) * 3;
        px[ri] = p[0]; py[ri] = p[1]; pz[ri] = p[2];
        n2[ri] = fmaf(px[ri], px[ri], fmaf(py[ri], py[ri], pz[ri] * pz[ri]));
        dens[ri] = 0.f;
    }
    const uint16_t* fhb = g_fhT + (size_t)bs * CC * VV + voff;
    const float4*   vnb = g_vn + (size_t)bs * VV + voff;

    float acc[2][8][4];
#pragma unroll
    for (int m = 0; m < 2; m++)
#pragma unroll
        for (int t = 0; t < 8; t++)
#pragma unroll
            for (int i = 0; i < 4; i++) acc[m][t][i] = 0.f;

    auto stage_cp = [&](int ch) {
        const uint32_t dst = sb + (uint32_t)(ch & 1) * STG;
#pragma unroll
        for (int i = 0; i < 4; i++) {
            int idx = tid + i * 128;
            int c = idx >> 3, u = idx & 7;
            cp16(dst + c * 128 + ((u * 16) ^ ((c & 7) * 16)),
                 fhb + (size_t)c * VV + ch * 64 + u * 8);
        }
        if (tid < 64) cp16(dst + 8192 + tid * 16, vnb + ch * 64 + tid);
        asm volatile("cp.async.commit_group;");
    };

    stage_cp(0);
    stage_cp(1);

    const uint32_t bswz = (uint32_t)((lane >> 2) << 4);
    const uint32_t koff = (uint32_t)((lane & 3) * 8);

    for (int ch = 0; ch < NCH; ch++) {
        const int s = ch & 1;
        if (ch == NCH - 1) asm volatile("cp.async.wait_group 0;");
        else               asm volatile("cp.async.wait_group 1;");
        __syncthreads();

        const uint32_t fbase = sb + (uint32_t)s * STG;
        const float4* vns = (const float4*)(smem + (size_t)s * STG + 8192);

#pragma unroll 1
        for (int kk = 0; kk < 4; kk++) {
            float4 vq[4];
#pragma unroll
            for (int j = 0; j < 4; j++) vq[j] = vns[kk * 16 + (lane & 3) * 4 + j];

            uint32_t HI[4][2];
#pragma unroll
            for (int ri = 0; ri < 4; ri++) {
                float w[4];
#pragma unroll
                for (int j = 0; j < 4; j++) {
                    float t  = fmaf(px[ri], vq[j].x, fmaf(py[ri], vq[j].y, pz[ri] * vq[j].z));
                    float d2 = fmaxf(fmaf(-2.f, t, n2[ri] + vq[j].w), 0.f);
                    float d; asm("sqrt.approx.f32 %0,%1;" : "=f"(d) : "f"(d2));
                    float e; asm("ex2.approx.f32 %0,%1;" : "=f"(e) : "f"(d * -0.57707801635558535f));
                    w[j] = e; dens[ri] += e;
                }
                HI[ri][0] = packh2(w[0], w[1]);
                HI[ri][1] = packh2(w[2], w[3]);
            }

            const uint32_t kb = (uint32_t)(kk * 32 + koff) ^ bswz;
#pragma unroll
            for (int t = 0; t < 8; t++) {
                const uint32_t addr = fbase + (uint32_t)((t * 8 + (lane >> 2)) * 128) + kb;
                uint32_t bh0, bh1;
                lds64(bh0, bh1, addr);
                mma16816(acc[0][t], HI[0][0], HI[1][0], HI[0][1], HI[1][1], bh0, bh1);
                mma16816(acc[1][t], HI[2][0], HI[3][0], HI[2][1], HI[3][1], bh0, bh1);
            }
        }
        __syncthreads();
        if (ch + 2 < NCH) stage_cp(ch + 2);
    }

#pragma unroll
    for (int ri = 0; ri < 4; ri++) {
        dens[ri] += __shfl_xor_sync(0xFFFFFFFFu, dens[ri], 1);
        dens[ri] += __shfl_xor_sync(0xFFFFFFFFu, dens[ri], 2);
    }

#pragma unroll
    for (int ri = 0; ri < 4; ri++) {
        const size_t q = (size_t)b * LL + rbase + ri * 8;
        float* orow = g_part + ((size_t)vh * NQ + q) * RX + side * 68;
        const int mt = ri >> 1, rp = (ri & 1) * 2;
#pragma unroll
        for (int t = 0; t < 8; t++) {
            float2 v2;
            v2.x = acc[mt][t][rp + 0];
            v2.y = acc[mt][t][rp + 1];
            *(float2*)(orow + t * 8 + (lane & 3) * 2) = v2;
        }
        if ((lane & 3) == 0) orow[64] = dens[ri];
    }
}

// ---------------- MLP: combine partials, normalize, 130->130 relu ->1 ----------------
__global__ void __launch_bounds__(256) mlp_kernel(const float* __restrict__ b2,
                                                  float* __restrict__ out) {
    __shared__ float xs[8][4][132];
    const int warp = threadIdx.x >> 5;
    const int lane = threadIdx.x & 31;
    const int q0 = (blockIdx.x * 8 + warp) * 4;

#pragma unroll
    for (int qq = 0; qq < 4; qq++) {
        const size_t q = q0 + qq;
        float v[5];
#pragma unroll
        for (int m = 0; m < 5; m++) {
            const int c = lane + 32 * m;
            float sum = 0.f;
            if (c < 130) {
                const int pc = c < 65 ? c : c + 3;
#pragma unroll
                for (int s = 0; s < NVH; s++)
                    sum += g_part[((size_t)s * NQ + q) * RX + pc];
            }
            v[m] = sum;
        }
        const float dl = __shfl_sync(0xFFFFFFFFu, v[2], 0);
        const float dr = __shfl_sync(0xFFFFFFFFu, v[4], 1);
        const float il = 1.f / dl, ir = 1.f / dr;
#pragma unroll
        for (int m = 0; m < 5; m++) {
            const int c = lane + 32 * m;
            if (c < 64)        xs[warp][qq][c] = v[m] * il;
            else if (c == 64)  xs[warp][qq][64] = dl;
            else if (c < 129)  xs[warp][qq][c] = v[m] * ir;
            else if (c == 129) xs[warp][qq][129] = dr;
        }
    }
    __syncwarp();

    const float4* wv = (const float4*)g_w1t;
    float4 hA[4], hB[4];
#pragma unroll
    for (int qq = 0; qq < 4; qq++) { hA[qq] = make_float4(0, 0, 0, 0); hB[qq] = hA[qq]; }
#pragma unroll 2
    for (int k = 0; k < 130; k++) {
        const float4 wA = wv[k * 33 + lane];
        const float4 wB = wv[k * 33 + 32];
#pragma unroll
        for (int qq = 0; qq < 4; qq++) {
            const float x = xs[warp][qq][k];
            hA[qq].x = fmaf(wA.x, x, hA[qq].x); hA[qq].y = fmaf(wA.y, x, hA[qq].y);
            hA[qq].z = fmaf(wA.z, x, hA[qq].z); hA[qq].w = fmaf(wA.w, x, hA[qq].w);
            hB[qq].x = fmaf(wB.x, x, hB[qq].x); hB[qq].y = fmaf(wB.y, x, hB[qq].y);
            hB[qq].z = fmaf(wB.z, x, hB[qq].z); hB[qq].w = fmaf(wB.w, x, hB[qq].w);
        }
    }
    const float4 b1A = ((const float4*)g_b1p)[lane];
    const float4 w2A = ((const float4*)g_w2p)[lane];
    const float4 b1B = ((const float4*)g_b1p)[32];
    const float4 w2B = ((const float4*)g_w2p)[32];
    const float bb = b2[0];

#pragma unroll
    for (int qq = 0; qq < 4; qq++) {
        float r = fmaxf(hA[qq].x + b1A.x, 0.f) * w2A.x + fmaxf(hA[qq].y + b1A.y, 0.f) * w2A.y
                + fmaxf(hA[qq].z + b1A.z, 0.f) * w2A.z + fmaxf(hA[qq].w + b1A.w, 0.f) * w2A.w;
        if (lane == 0)
            r += fmaxf(hB[qq].x + b1B.x, 0.f) * w2B.x + fmaxf(hB[qq].y + b1B.y, 0.f) * w2B.y
               + fmaxf(hB[qq].z + b1B.z, 0.f) * w2B.z + fmaxf(hB[qq].w + b1B.w, 0.f) * w2B.w;
#pragma unroll
        for (int o = 16; o > 0; o >>= 1) r += __shfl_xor_sync(0xFFFFFFFFu, r, o);
        if (lane == 0) out[q0 + qq] = r + bb;
    }
}

extern "C" void kernel_launch(void* const* d_in, const int* in_sizes, int n_in,
                              void* d_out, int out_size) {
    (void)in_sizes; (void)n_in; (void)out_size;
    const float* locsL  = (const float*)d_in[0];
    const float* locsR  = (const float*)d_in[1];
    const float* vertsL = (const float*)d_in[2];
    const float* vertsR = (const float*)d_in[3];
    const float* featsL = (const float*)d_in[4];
    const float* featsR = (const float*)d_in[5];
    const float* w1     = (const float*)d_in[6];
    const float* b1     = (const float*)d_in[7];
    const float* w2     = (const float*)d_in[8];
    const float* b2     = (const float*)d_in[9];
    float* out = (float*)d_out;

    prep_vn_kernel<<<dim3(VV / 256, 16), 256>>>(vertsL, vertsR);
    prep_feats_kernel<<<dim3(VV / 64, 16), 256>>>(featsL, featsR);
    prep_w1_kernel<<<69, 256>>>(w1, b1, w2);
    interp_kernel<<<dim3(LL / 128, 16, NVH), 128>>>(locsL, locsR);
    mlp_kernel<<<NQ / 32, 256>>>(b2, out);
}

// round 8
// speedup vs baseline: 5.4800x; 1.1208x over previous
#include <cuda_runtime.h>
#include <cuda_fp16.h>
#include <cstdint>

#define BB 8
#define LL 2048
#define VV 8192
#define CC 64
#define NQ (BB * LL)
#define NVH 8
#define VH (VV / NVH)        // 1024 verts per CTA
#define NCH (VH / 64)        // 16 chunks of 64 verts
#define RX 136

static __device__ float    g_part[(size_t)NVH * NQ * RX];   // [vh][q][136]
static __device__ float4   g_vn[2 * BB * VV];                // (-2x,-2y,-2z,|v|^2), permuted
static __device__ uint16_t g_fhT[(size_t)2 * BB * CC * VV];  // fp16 feats^T, [bs][c][vslot]
static __device__ float    g_w1t[132 * 132];
static __device__ float    g_b1p[132];
static __device__ float    g_w2p[132];

// slot permutation within each 16-vert group (k-major mma B fragment via lds64)
__host__ __device__ __forceinline__ int inv16(int k) {
    return ((k >> 1) & 3) * 4 + (k & 1) + ((k >> 3) << 1);
}

__device__ __forceinline__ void cp16(uint32_t d, const void* s) {
    asm volatile("cp.async.cg.shared.global [%0], [%1], 16;" :: "r"(d), "l"(s));
}
__device__ __forceinline__ void lds64(uint32_t& a, uint32_t& b, uint32_t addr) {
    asm volatile("ld.shared.v2.b32 {%0,%1}, [%2];" : "=r"(a), "=r"(b) : "r"(addr));
}
__device__ __forceinline__ uint32_t packh2(float lo, float hi) {
    uint32_t r;
    asm("cvt.rn.f16x2.f32 %0, %1, %2;" : "=r"(r) : "f"(hi), "f"(lo));
    return r;
}
__device__ __forceinline__ uint32_t ex2h2(uint32_t a) {
    uint32_t r;
    asm("ex2.approx.f16x2 %0, %1;" : "=r"(r) : "r"(a));
    return r;
}
__device__ __forceinline__ void mma16816(float* d, uint32_t a0, uint32_t a1, uint32_t a2,
                                         uint32_t a3, uint32_t b0, uint32_t b1) {
    asm volatile(
        "mma.sync.aligned.m16n8k16.row.col.f32.f16.f16.f32 "
        "{%0,%1,%2,%3},{%4,%5,%6,%7},{%8,%9},{%0,%1,%2,%3};"
        : "+f"(d[0]), "+f"(d[1]), "+f"(d[2]), "+f"(d[3])
        : "r"(a0), "r"(a1), "r"(a2), "r"(a3), "r"(b0), "r"(b1));
}

// ---------------- preps ----------------
__global__ void prep_vn_kernel(const float* __restrict__ vL, const float* __restrict__ vR) {
    const int v = blockIdx.x * 256 + threadIdx.x;
    const int bs = blockIdx.y, b = bs >> 1, side = bs & 1;
    const float* vp = (side ? vR : vL) + ((size_t)b * VV + v) * 3;
    const float x = vp[0], y = vp[1], z = vp[2];
    const int vs = (v & ~15) | inv16(v & 15);
    g_vn[(size_t)bs * VV + vs] =
        make_float4(-2.f * x, -2.f * y, -2.f * z, fmaf(x, x, fmaf(y, y, z * z)));
}

__global__ void prep_feats_kernel(const float* __restrict__ fL, const float* __restrict__ fR) {
    __shared__ float tile[64][65];
    const int vt = blockIdx.x, bs = blockIdx.y, b = bs >> 1, side = bs & 1;
    const int tid = threadIdx.x;
    const float* src = (side ? fR : fL) + ((size_t)b * VV + (size_t)vt * 64) * CC;
#pragma unroll
    for (int i = 0; i < 16; i++) {
        int idx = tid + 256 * i;
        tile[idx >> 6][idx & 63] = src[idx];
    }
    __syncthreads();
#pragma unroll
    for (int i = 0; i < 16; i++) {
        int idx = tid + 256 * i;
        int c = idx >> 6, v = idx & 63;
        int vs = (v & ~15) | inv16(v & 15);
        g_fhT[((size_t)bs * CC + c) * VV + (size_t)vt * 64 + vs] =
            __half_as_ushort(__float2half_rn(tile[v][c]));
    }
}

__global__ void prep_w1_kernel(const float* __restrict__ w1, const float* __restrict__ b1,
                               const float* __restrict__ w2) {
    const int idx = blockIdx.x * 256 + threadIdx.x;
    if (idx < 132 * 132) {
        const int k = idx / 132, j = idx % 132;
        g_w1t[idx] = (j < 130 && k < 130) ? w1[j * 130 + k] : 0.f;
    }
    if (blockIdx.x == 0 && idx < 132) {
        g_b1p[idx] = (idx < 130) ? b1[idx] : 0.f;
        g_w2p[idx] = (idx < 130) ? w2[idx] : 0.f;
    }
}

// ---------------- fused interp: W-gen + mma.sync fp16, dens via ones-column ----------------
// grid (LL/128, 16, NVH), block 128 (4 warps, each M=32 x N=65)
// stage layout: feats rows 0..63 @0 (8192B), ones row 64 @8192 (128B),
//               zero rows 65..71 @8320 (896B), vn @9216 (1024B)
#define STG 10240

__global__ void __launch_bounds__(128, 4)
interp_kernel(const float* __restrict__ locsL, const float* __restrict__ locsR) {
    __shared__ __align__(1024) char smem[2 * STG];
    const uint32_t sb = (uint32_t)__cvta_generic_to_shared(smem);
    const int tid = threadIdx.x, lane = tid & 31, warp = tid >> 5;
    const int lt = blockIdx.x, bs = blockIdx.y, vh = blockIdx.z;
    const int b = bs >> 1, side = bs & 1;
    const int voff = vh * VH;

    // one-time: ones row (fp16 1.0 pairs) + zero pad rows, both stages
#pragma unroll
    for (int i = tid; i < 64; i += 128)
        ((uint32_t*)(smem + (i >> 5) * STG + 8192))[i & 31] = 0x3C003C00u;
    for (int i = tid; i < 448; i += 128)
        ((uint32_t*)(smem + (i / 224) * STG + 8320))[i % 224] = 0u;

    const float* locs = (side ? locsR : locsL) + (size_t)b * LL * 3;
    float px[4], py[4], pz[4], n2[4];
    const int rbase = lt * 128 + warp * 32 + (lane >> 2);
#pragma unroll
    for (int ri = 0; ri < 4; ri++) {
        const float* p = locs + (size_t)(rbase + ri * 8) * 3;
        px[ri] = p[0]; py[ri] = p[1]; pz[ri] = p[2];
        n2[ri] = fmaf(px[ri], px[ri], fmaf(py[ri], py[ri], pz[ri] * pz[ri]));
    }
    const uint16_t* fhb = g_fhT + (size_t)bs * CC * VV + voff;
    const float4*   vnb = g_vn + (size_t)bs * VV + voff;

    float acc[2][9][4];
#pragma unroll
    for (int m = 0; m < 2; m++)
#pragma unroll
        for (int t = 0; t < 9; t++)
#pragma unroll
            for (int i = 0; i < 4; i++) acc[m][t][i] = 0.f;

    auto stage_cp = [&](int ch) {
        const uint32_t dst = sb + (uint32_t)(ch & 1) * STG;
#pragma unroll
        for (int i = 0; i < 4; i++) {
            int idx = tid + i * 128;
            int c = idx >> 3, u = idx & 7;
            cp16(dst + c * 128 + ((u * 16) ^ ((c & 7) * 16)),
                 fhb + (size_t)c * VV + ch * 64 + u * 8);
        }
        if (tid < 64) cp16(dst + 9216 + tid * 16, vnb + ch * 64 + tid);
        asm volatile("cp.async.commit_group;");
    };

    stage_cp(0);
    stage_cp(1);

    const uint32_t bswz = (uint32_t)((lane >> 2) << 4);
    const uint32_t koff = (uint32_t)((lane & 3) * 8);

    for (int ch = 0; ch < NCH; ch++) {
        const int s = ch & 1;
        if (ch == NCH - 1) asm volatile("cp.async.wait_group 0;");
        else               asm volatile("cp.async.wait_group 1;");
        __syncthreads();

        const uint32_t fbase = sb + (uint32_t)s * STG;
        const float4* vns = (const float4*)(smem + (size_t)s * STG + 9216);

#pragma unroll 1
        for (int kk = 0; kk < 4; kk++) {
            float4 vq[4];
#pragma unroll
            for (int j = 0; j < 4; j++) vq[j] = vns[kk * 16 + (lane & 3) * 4 + j];

            uint32_t HI[4][2];
#pragma unroll
            for (int ri = 0; ri < 4; ri++) {
                float arg[4];
#pragma unroll
                for (int j = 0; j < 4; j++) {
                    float s0 = n2[ri] + vq[j].w;
                    float d2 = fmaf(px[ri], vq[j].x,
                               fmaf(py[ri], vq[j].y,
                               fmaf(pz[ri], vq[j].z, s0)));
                    d2 = fmaxf(d2, 0.f);
                    float d; asm("sqrt.approx.f32 %0,%1;" : "=f"(d) : "f"(d2));
                    arg[j] = d * -0.57707801635558535f;   // -log2(e)/sigma
                }
                HI[ri][0] = ex2h2(packh2(arg[0], arg[1]));
                HI[ri][1] = ex2h2(packh2(arg[2], arg[3]));
            }

            const uint32_t kb = (uint32_t)(kk * 32 + koff) ^ bswz;
#pragma unroll
            for (int t = 0; t < 9; t++) {
                const uint32_t addr = fbase + (uint32_t)((t * 8 + (lane >> 2)) * 128) + kb;
                uint32_t bh0, bh1;
                lds64(bh0, bh1, addr);
                mma16816(acc[0][t], HI[0][0], HI[1][0], HI[0][1], HI[1][1], bh0, bh1);
                mma16816(acc[1][t], HI[2][0], HI[3][0], HI[2][1], HI[3][1], bh0, bh1);
            }
        }
        __syncthreads();
        if (ch + 2 < NCH) stage_cp(ch + 2);
    }

    // write unnormalized partials + dens (dens = D column 64, held by lane&3==0)
#pragma unroll
    for (int ri = 0; ri < 4; ri++) {
        const size_t q = (size_t)b * LL + rbase + ri * 8;
        float* orow = g_part + ((size_t)vh * NQ + q) * RX + side * 68;
        const int mt = ri >> 1, rp = (ri & 1) * 2;
#pragma unroll
        for (int t = 0; t < 8; t++) {
            float2 v2;
            v2.x = acc[mt][t][rp + 0];
            v2.y = acc[mt][t][rp + 1];
            *(float2*)(orow + t * 8 + (lane & 3) * 2) = v2;
        }
        if ((lane & 3) == 0) orow[64] = acc[mt][8][rp];
    }
}

// ---------------- MLP: combine partials, normalize, 130->130 relu ->1 ----------------
__global__ void __launch_bounds__(256) mlp_kernel(const float* __restrict__ b2,
                                                  float* __restrict__ out) {
    __shared__ float xs[8][4][132];
    const int warp = threadIdx.x >> 5;
    const int lane = threadIdx.x & 31;
    const int q0 = (blockIdx.x * 8 + warp) * 4;

#pragma unroll
    for (int qq = 0; qq < 4; qq++) {
        const size_t q = q0 + qq;
        float v[5];
#pragma unroll
        for (int m = 0; m < 5; m++) {
            const int c = lane + 32 * m;
            float sum = 0.f;
            if (c < 130) {
                const int pc = c < 65 ? c : c + 3;
#pragma unroll
                for (int s = 0; s < NVH; s++)
                    sum += g_part[((size_t)s * NQ + q) * RX + pc];
            }
            v[m] = sum;
        }
        const float dl = __shfl_sync(0xFFFFFFFFu, v[2], 0);
        const float dr = __shfl_sync(0xFFFFFFFFu, v[4], 1);
        const float il = 1.f / dl, ir = 1.f / dr;
#pragma unroll
        for (int m = 0; m < 5; m++) {
            const int c = lane + 32 * m;
            if (c < 64)        xs[warp][qq][c] = v[m] * il;
            else if (c == 64)  xs[warp][qq][64] = dl;
            else if (c < 129)  xs[warp][qq][c] = v[m] * ir;
            else if (c == 129) xs[warp][qq][129] = dr;
        }
    }
    __syncwarp();

    const float4* wv = (const float4*)g_w1t;
    float4 hA[4], hB[4];
#pragma unroll
    for (int qq = 0; qq < 4; qq++) { hA[qq] = make_float4(0, 0, 0, 0); hB[qq] = hA[qq]; }
#pragma unroll 2
    for (int k = 0; k < 130; k++) {
        const float4 wA = wv[k * 33 + lane];
        const float4 wB = wv[k * 33 + 32];
#pragma unroll
        for (int qq = 0; qq < 4; qq++) {
            const float x = xs[warp][qq][k];
            hA[qq].x = fmaf(wA.x, x, hA[qq].x); hA[qq].y = fmaf(wA.y, x, hA[qq].y);
            hA[qq].z = fmaf(wA.z, x, hA[qq].z); hA[qq].w = fmaf(wA.w, x, hA[qq].w);
            hB[qq].x = fmaf(wB.x, x, hB[qq].x); hB[qq].y = fmaf(wB.y, x, hB[qq].y);
            hB[qq].z = fmaf(wB.z, x, hB[qq].z); hB[qq].w = fmaf(wB.w, x, hB[qq].w);
        }
    }
    const float4 b1A = ((const float4*)g_b1p)[lane];
    const float4 w2A = ((const float4*)g_w2p)[lane];
    const float4 b1B = ((const float4*)g_b1p)[32];
    const float4 w2B = ((const float4*)g_w2p)[32];
    const float bb = b2[0];

#pragma unroll
    for (int qq = 0; qq < 4; qq++) {
        float r = fmaxf(hA[qq].x + b1A.x, 0.f) * w2A.x + fmaxf(hA[qq].y + b1A.y, 0.f) * w2A.y
                + fmaxf(hA[qq].z + b1A.z, 0.f) * w2A.z + fmaxf(hA[qq].w + b1A.w, 0.f) * w2A.w;
        if (lane == 0)
            r += fmaxf(hB[qq].x + b1B.x, 0.f) * w2B.x + fmaxf(hB[qq].y + b1B.y, 0.f) * w2B.y
               + fmaxf(hB[qq].z + b1B.z, 0.f) * w2B.z + fmaxf(hB[qq].w + b1B.w, 0.f) * w2B.w;
#pragma unroll
        for (int o = 16; o > 0; o >>= 1) r += __shfl_xor_sync(0xFFFFFFFFu, r, o);
        if (lane == 0) out[q0 + qq] = r + bb;
    }
}

extern "C" void kernel_launch(void* const* d_in, const int* in_sizes, int n_in,
                              void* d_out, int out_size) {
    (void)in_sizes; (void)n_in; (void)out_size;
    const float* locsL  = (const float*)d_in[0];
    const float* locsR  = (const float*)d_in[1];
    const float* vertsL = (const float*)d_in[2];
    const float* vertsR = (const float*)d_in[3];
    const float* featsL = (const float*)d_in[4];
    const float* featsR = (const float*)d_in[5];
    const float* w1     = (const float*)d_in[6];
    const float* b1     = (const float*)d_in[7];
    const float* w2     = (const float*)d_in[8];
    const float* b2     = (const float*)d_in[9];
    float* out = (float*)d_out;

    prep_vn_kernel<<<dim3(VV / 256, 16), 256>>>(vertsL, vertsR);
    prep_feats_kernel<<<dim3(VV / 64, 16), 256>>>(featsL, featsR);
    prep_w1_kernel<<<69, 256>>>(w1, b1, w2);
    interp_kernel<<<dim3(LL / 128, 16, NVH), 128>>>(locsL, locsR);
    mlp_kernel<<<NQ / 32, 256>>>(b2, out);
}